// round 1
// baseline (speedup 1.0000x reference)
#include <cuda_runtime.h>
#include <cstdint>

#define NNODES 50000
#define FDIM   128
#define BN_EPS 1e-5f

// ---------------- scratch (static device globals; no runtime alloc) ----------------
__device__ float g_agg[NNODES * FDIM];   // scatter accumulator
__device__ float g_h1 [NNODES * FDIM];   // layer-0 output
__device__ float g_h2 [NNODES * FDIM];   // layer-1 output
__device__ float g_cnt[NNODES];          // in-degree (float)
__device__ float g_stats[2 * FDIM];      // [0..127]=colsum, [128..255]=colsumsq
__device__ float g_scale[FDIM];          // BN fused scale
__device__ float g_shift[FDIM];          // BN fused shift

// ---------------- helpers ----------------
__device__ __forceinline__ void red_add_f32x4(float* addr, float4 v) {
    asm volatile("red.global.add.v4.f32 [%0], {%1,%2,%3,%4};"
                 :: "l"(addr), "f"(v.x), "f"(v.y), "f"(v.z), "f"(v.w)
                 : "memory");
}

__global__ void zero_kernel(float4* __restrict__ p, int n4) {
    int i = blockIdx.x * blockDim.x + threadIdx.x;
    if (i < n4) p[i] = make_float4(0.f, 0.f, 0.f, 0.f);
}

__global__ void count_kernel(const int* __restrict__ dst, int E) {
    int i = blockIdx.x * blockDim.x + threadIdx.x;
    if (i < E) atomicAdd(&g_cnt[dst[i]], 1.0f);
}

// One warp per edge: 32 lanes x float4 = 128 floats per row.
__global__ void scatter_kernel(const float4* __restrict__ h,
                               const int* __restrict__ src,
                               const int* __restrict__ dst,
                               const float* __restrict__ w, int E) {
    int g    = blockIdx.x * blockDim.x + threadIdx.x;
    int e    = g >> 5;
    int lane = g & 31;
    if (e >= E) return;
    int   s  = src[e];
    int   d  = dst[e];
    float we = w[e];
    float4 v = h[(size_t)s * (FDIM / 4) + lane];
    v.x *= we; v.y *= we; v.z *= we; v.w *= we;
    red_add_f32x4(&g_agg[(size_t)d * FDIM + lane * 4], v);
}

// out[row, ct*64 .. ct*64+63] = (agg[row]/max(cnt,1)) @ Wl + h[row] @ Wr + b
// One thread per row; 64-column tile of both weight mats staged in smem.
template <int F_OUT>
__global__ void __launch_bounds__(128)
gemm_kernel(const float4* __restrict__ hin,
            const float* __restrict__ Wl,
            const float* __restrict__ Wr,
            const float* __restrict__ b,
            float* __restrict__ out) {
    constexpr int F_IN = FDIM;
    extern __shared__ float smem[];
    float* Wls = smem;               // [F_IN][64]
    float* Wrs = smem + F_IN * 64;   // [F_IN][64]

    const int ct = blockIdx.y;       // column tile index
    for (int i = threadIdx.x; i < F_IN * 64; i += 128) {
        int r = i >> 6, c = i & 63;
        Wls[i] = Wl[r * F_OUT + ct * 64 + c];
        Wrs[i] = Wr[r * F_OUT + ct * 64 + c];
    }
    __syncthreads();

    int row = blockIdx.x * 128 + threadIdx.x;
    if (row >= NNODES) return;

    float invc = 1.0f / fmaxf(g_cnt[row], 1.0f);
    const float4* ar = (const float4*)&g_agg[(size_t)row * F_IN];
    const float4* hr = hin + (size_t)row * (F_IN / 4);

    float acc[64];
#pragma unroll
    for (int j = 0; j < 64; j++) acc[j] = 0.f;

#pragma unroll 1
    for (int k4 = 0; k4 < F_IN / 4; k4++) {
        float4 m  = ar[k4];
        float4 xv = hr[k4];
        float ma[4] = {m.x * invc, m.y * invc, m.z * invc, m.w * invc};
        float xa[4] = {xv.x, xv.y, xv.z, xv.w};
#pragma unroll
        for (int kk = 0; kk < 4; kk++) {
            const float4* wl4 = (const float4*)&Wls[(k4 * 4 + kk) * 64];
            const float4* wr4 = (const float4*)&Wrs[(k4 * 4 + kk) * 64];
#pragma unroll
            for (int j4 = 0; j4 < 16; j4++) {
                float4 wl = wl4[j4];
                float4 wr = wr4[j4];
                acc[4 * j4 + 0] += ma[kk] * wl.x + xa[kk] * wr.x;
                acc[4 * j4 + 1] += ma[kk] * wl.y + xa[kk] * wr.y;
                acc[4 * j4 + 2] += ma[kk] * wl.z + xa[kk] * wr.z;
                acc[4 * j4 + 3] += ma[kk] * wl.w + xa[kk] * wr.w;
            }
        }
    }

    float4* o = (float4*)&out[(size_t)row * F_OUT + ct * 64];
    const float4* b4 = (const float4*)&b[ct * 64];
#pragma unroll
    for (int j4 = 0; j4 < 16; j4++) {
        float4 bb = b4[j4];
        o[j4] = make_float4(acc[4 * j4 + 0] + bb.x,
                            acc[4 * j4 + 1] + bb.y,
                            acc[4 * j4 + 2] + bb.z,
                            acc[4 * j4 + 3] + bb.w);
    }
}

// Per-column sum and sum of squares over N rows.
__global__ void stats_kernel(const float* __restrict__ h) {
    int c = threadIdx.x;  // 0..127
    float s = 0.f, q = 0.f;
    for (int r = blockIdx.x; r < NNODES; r += gridDim.x) {
        float v = h[(size_t)r * FDIM + c];
        s += v;
        q += v * v;
    }
    atomicAdd(&g_stats[c], s);
    atomicAdd(&g_stats[FDIM + c], q);
}

__global__ void bnparams_kernel(const float* __restrict__ gamma,
                                const float* __restrict__ beta) {
    int c = threadIdx.x;  // 128 threads
    const float invN = 1.0f / (float)NNODES;
    float mu  = g_stats[c] * invN;
    float var = g_stats[FDIM + c] * invN - mu * mu;
    float a   = gamma[c] * rsqrtf(var + BN_EPS);
    g_scale[c] = a;
    g_shift[c] = beta[c] - mu * a;
}

__global__ void bnrelu_kernel(float4* __restrict__ h, int n4) {
    int i = blockIdx.x * blockDim.x + threadIdx.x;
    if (i >= n4) return;
    int c4 = i & (FDIM / 4 - 1);
    float4 a = ((const float4*)g_scale)[c4];
    float4 s = ((const float4*)g_shift)[c4];
    float4 v = h[i];
    v.x = fmaxf(a.x * v.x + s.x, 0.f);
    v.y = fmaxf(a.y * v.y + s.y, 0.f);
    v.z = fmaxf(a.z * v.z + s.z, 0.f);
    v.w = fmaxf(a.w * v.w + s.w, 0.f);
    h[i] = v;
}

// ---------------- launch ----------------
extern "C" void kernel_launch(void* const* d_in, const int* in_sizes, int n_in,
                              void* d_out, int out_size) {
    const float* x      = (const float*)d_in[0];
    const int*   ei     = (const int*)d_in[1];
    const float* ew     = (const float*)d_in[2];
    const float* Wl0    = (const float*)d_in[3];
    const float* Wr0    = (const float*)d_in[4];
    const float* b0     = (const float*)d_in[5];
    const float* Wl1    = (const float*)d_in[6];
    const float* Wr1    = (const float*)d_in[7];
    const float* b1     = (const float*)d_in[8];
    const float* Wl2    = (const float*)d_in[9];
    const float* Wr2    = (const float*)d_in[10];
    const float* b2     = (const float*)d_in[11];
    const float* gamma0 = (const float*)d_in[12];
    const float* beta0  = (const float*)d_in[13];
    const float* gamma1 = (const float*)d_in[14];
    const float* beta1  = (const float*)d_in[15];
    float* out = (float*)d_out;

    const int E = in_sizes[2];
    const int* src = ei;
    const int* dst = ei + E;

    float *agg, *h1, *h2, *cnt, *stats;
    cudaGetSymbolAddress((void**)&agg,   g_agg);
    cudaGetSymbolAddress((void**)&h1,    g_h1);
    cudaGetSymbolAddress((void**)&h2,    g_h2);
    cudaGetSymbolAddress((void**)&cnt,   g_cnt);
    cudaGetSymbolAddress((void**)&stats, g_stats);

    const int SMEM = FDIM * 64 * 2 * (int)sizeof(float);  // 65536
    cudaFuncSetAttribute(gemm_kernel<128>, cudaFuncAttributeMaxDynamicSharedMemorySize, SMEM);
    cudaFuncSetAttribute(gemm_kernel<64>,  cudaFuncAttributeMaxDynamicSharedMemorySize, SMEM);

    auto zero = [&](float* p, int n) {
        int n4 = n / 4;
        zero_kernel<<<(n4 + 255) / 256, 256>>>((float4*)p, n4);
    };

    const int scatterBlocks = (E * 32 + 255) / 256;
    const int bnN4          = NNODES * (FDIM / 4);
    const dim3 gGrid128((NNODES + 127) / 128, 2);
    const dim3 gGrid64 ((NNODES + 127) / 128, 1);

    // in-degree (shared by all 3 layers)
    zero(cnt, NNODES);
    count_kernel<<<(E + 255) / 256, 256>>>(dst, E);

    // ---- layer 0 ----
    zero(agg, NNODES * FDIM);
    scatter_kernel<<<scatterBlocks, 256>>>((const float4*)x, src, dst, ew, E);
    gemm_kernel<128><<<gGrid128, 128, SMEM>>>((const float4*)x, Wl0, Wr0, b0, h1);
    zero(stats, 2 * FDIM);
    stats_kernel<<<1024, 128>>>(h1);
    bnparams_kernel<<<1, 128>>>(gamma0, beta0);
    bnrelu_kernel<<<(bnN4 + 255) / 256, 256>>>((float4*)h1, bnN4);

    // ---- layer 1 ----
    zero(agg, NNODES * FDIM);
    scatter_kernel<<<scatterBlocks, 256>>>((const float4*)h1, src, dst, ew, E);
    gemm_kernel<128><<<gGrid128, 128, SMEM>>>((const float4*)h1, Wl1, Wr1, b1, h2);
    zero(stats, 2 * FDIM);
    stats_kernel<<<1024, 128>>>(h2);
    bnparams_kernel<<<1, 128>>>(gamma1, beta1);
    bnrelu_kernel<<<(bnN4 + 255) / 256, 256>>>((float4*)h2, bnN4);

    // ---- layer 2 ----
    zero(agg, NNODES * FDIM);
    scatter_kernel<<<scatterBlocks, 256>>>((const float4*)h2, src, dst, ew, E);
    gemm_kernel<64><<<gGrid64, 128, SMEM>>>((const float4*)h2, Wl2, Wr2, b2, out);
}

// round 2
// speedup vs baseline: 1.2801x; 1.2801x over previous
#include <cuda_runtime.h>
#include <cstdint>

#define NNODES 50000
#define FDIM   128
#define BN_EPS 1e-5f

// ---------------- scratch (static device globals; no runtime alloc) ----------------
__device__ float g_agg[NNODES * FDIM];   // scatter accumulator
__device__ float g_h1 [NNODES * FDIM];   // layer-0 output
__device__ float g_h2 [NNODES * FDIM];   // layer-1 output
__device__ float g_cnt[NNODES];          // in-degree (float)
__device__ float g_stats[2 * FDIM];      // [0..127]=colsum, [128..255]=colsumsq
__device__ float g_scale[FDIM];          // BN fused scale
__device__ float g_shift[FDIM];          // BN fused shift
// packed tf32 hi/lo weights (fragment order), 3 layers: 32768 + 32768 + 16384
__device__ float g_wph[81920];
__device__ float g_wpl[81920];

// ---------------- helpers ----------------
__device__ __forceinline__ void red_add_f32x4(float* addr, float4 v) {
    asm volatile("red.global.add.v4.f32 [%0], {%1,%2,%3,%4};"
                 :: "l"(addr), "f"(v.x), "f"(v.y), "f"(v.z), "f"(v.w)
                 : "memory");
}

__device__ __forceinline__ uint32_t f2tf(float f) {
    uint32_t r;
    asm("cvt.rna.tf32.f32 %0, %1;" : "=r"(r) : "f"(f));
    return r;
}

__device__ __forceinline__ void mma_tf32(float* d, const uint32_t* a, const uint32_t* b) {
    asm volatile("mma.sync.aligned.m16n8k8.row.col.f32.tf32.tf32.f32 "
                 "{%0,%1,%2,%3}, {%4,%5,%6,%7}, {%8,%9}, {%0,%1,%2,%3};"
                 : "+f"(d[0]), "+f"(d[1]), "+f"(d[2]), "+f"(d[3])
                 : "r"(a[0]), "r"(a[1]), "r"(a[2]), "r"(a[3]),
                   "r"(b[0]), "r"(b[1]));
}

__global__ void zero_kernel(float4* __restrict__ p, int n4) {
    int i = blockIdx.x * blockDim.x + threadIdx.x;
    if (i < n4) p[i] = make_float4(0.f, 0.f, 0.f, 0.f);
}

__global__ void count_kernel(const int* __restrict__ dst, int E) {
    int i = blockIdx.x * blockDim.x + threadIdx.x;
    if (i < E) atomicAdd(&g_cnt[dst[i]], 1.0f);
}

// One warp per edge: 32 lanes x float4 = 128 floats per row.
__global__ void scatter_kernel(const float4* __restrict__ h,
                               const int* __restrict__ src,
                               const int* __restrict__ dst,
                               const float* __restrict__ w, int E) {
    int g    = blockIdx.x * blockDim.x + threadIdx.x;
    int e    = g >> 5;
    int lane = g & 31;
    if (e >= E) return;
    int   s  = src[e];
    int   d  = dst[e];
    float we = w[e];
    float4 v = h[(size_t)s * (FDIM / 4) + lane];
    v.x *= we; v.y *= we; v.z *= we; v.w *= we;
    red_add_f32x4(&g_agg[(size_t)d * FDIM + lane * 4], v);
}

// Pack stacked weights [Wl;Wr] (256 x NOUT) into mma-fragment-ordered tf32 hi/lo.
// Layout: [(chunk*4 + kstep)*NT + ntile]*64 + lane*2 + pair, pair selects (b0,b1).
__global__ void pack_w_kernel(const float* __restrict__ Wl,
                              const float* __restrict__ Wr,
                              int NOUT, float* __restrict__ wph,
                              float* __restrict__ wpl) {
    int idx = blockIdx.x * blockDim.x + threadIdx.x;
    if (idx >= 256 * NOUT) return;
    int k = idx / NOUT, n = idx % NOUT;
    float v = (k < 128) ? Wl[k * NOUT + n] : Wr[(k - 128) * NOUT + n];
    uint32_t hi = f2tf(v);
    uint32_t lo = f2tf(v - __uint_as_float(hi));
    int c = k >> 5, s = (k >> 3) & 3, kin = k & 7, t = n >> 3, nin = n & 7;
    int lanei = (nin << 2) | (kin & 3);
    int pair  = kin >> 2;
    int NT = NOUT / 8;
    int o = ((c * 4 + s) * NT + t) * 64 + lanei * 2 + pair;
    wph[o] = __uint_as_float(hi);
    wpl[o] = __uint_as_float(lo);
}

// Tensor-core dual GEMM: out = (agg/cnt) @ Wl + hin @ Wr + b
// Block: 128 rows x NOUT cols; 8 warps = 4(M) x 2(N); mma m16n8k8 tf32, 3xTF32.
template <int NOUT>
__global__ void __launch_bounds__(256)
gemm_tc(const float* __restrict__ hin,
        const float* __restrict__ wph,
        const float* __restrict__ wpl,
        const float* __restrict__ bias,
        float* __restrict__ out) {
    constexpr int NT  = NOUT / 8;   // total n-tiles
    constexpr int NTW = NT / 2;     // n-tiles per warp
    constexpr int CHUNK = 4 * NT * 64;  // floats per K-chunk per array

    extern __shared__ float smem[];
    float* sBh = smem;
    float* sBl = smem + CHUNK;

    const int tid  = threadIdx.x;
    const int wid  = tid >> 5;
    const int lane = tid & 31;
    const int wm   = wid & 3;    // warp row group
    const int wn   = wid >> 2;   // warp col group
    const int gid  = lane >> 2;  // group id (row within tile)
    const int tig  = lane & 3;   // thread in group (col within tile)

    const int rowBase = blockIdx.x * 128 + wm * 32;
    const int tb = wn * NTW;

    // invc for the 4 rows this thread touches (mt*16 + {0,8} + gid)
    float inv[4];
#pragma unroll
    for (int j = 0; j < 4; j++) {
        int r = rowBase + (j >> 1) * 16 + (j & 1) * 8 + gid;
        inv[j] = (r < NNODES) ? (1.0f / fmaxf(g_cnt[r], 1.0f)) : 0.0f;
    }

    float acc[2][NTW][4];
#pragma unroll
    for (int mt = 0; mt < 2; mt++)
#pragma unroll
        for (int t = 0; t < NTW; t++)
#pragma unroll
            for (int j = 0; j < 4; j++) acc[mt][t][j] = 0.f;

#pragma unroll 1
    for (int c = 0; c < 8; c++) {
        // stage packed B chunk (hi+lo) into smem
        __syncthreads();
        const float4* gh = (const float4*)(wph + c * CHUNK);
        const float4* gl = (const float4*)(wpl + c * CHUNK);
        float4* dh = (float4*)sBh;
        float4* dl = (float4*)sBl;
        for (int i = tid; i < CHUNK / 4; i += 256) { dh[i] = gh[i]; dl[i] = gl[i]; }
        __syncthreads();

        const bool meanPart = (c < 4);
        const float* Asrc = meanPart ? g_agg : hin;
        const int colBase = meanPart ? c * 32 : (c - 4) * 32;

#pragma unroll
        for (int s = 0; s < 4; s++) {
            const int col = colBase + s * 8 + tig;
            uint32_t ahi[2][4], alo[2][4];
#pragma unroll
            for (int mt = 0; mt < 2; mt++) {
                int r = rowBase + mt * 16 + gid;
                float a0 = (r < NNODES)     ? Asrc[(size_t)r * 128 + col]           : 0.f;
                float a1 = (r + 8 < NNODES) ? Asrc[(size_t)(r + 8) * 128 + col]     : 0.f;
                float a2 = (r < NNODES)     ? Asrc[(size_t)r * 128 + col + 4]       : 0.f;
                float a3 = (r + 8 < NNODES) ? Asrc[(size_t)(r + 8) * 128 + col + 4] : 0.f;
                if (meanPart) {
                    a0 *= inv[mt * 2];     a2 *= inv[mt * 2];
                    a1 *= inv[mt * 2 + 1]; a3 *= inv[mt * 2 + 1];
                }
                float av[4] = {a0, a1, a2, a3};
#pragma unroll
                for (int j = 0; j < 4; j++) {
                    ahi[mt][j] = f2tf(av[j]);
                    alo[mt][j] = f2tf(av[j] - __uint_as_float(ahi[mt][j]));
                }
            }
#pragma unroll
            for (int t = 0; t < NTW; t++) {
                float2 bh = *(const float2*)&sBh[(s * NT + tb + t) * 64 + lane * 2];
                float2 bl = *(const float2*)&sBl[(s * NT + tb + t) * 64 + lane * 2];
                uint32_t bhr[2] = {__float_as_uint(bh.x), __float_as_uint(bh.y)};
                uint32_t blr[2] = {__float_as_uint(bl.x), __float_as_uint(bl.y)};
#pragma unroll
                for (int mt = 0; mt < 2; mt++) {
                    mma_tf32(acc[mt][t], alo[mt], bhr);
                    mma_tf32(acc[mt][t], ahi[mt], blr);
                    mma_tf32(acc[mt][t], ahi[mt], bhr);
                }
            }
        }
    }

    // epilogue: add bias, store float2 per (row, tile)
#pragma unroll
    for (int mt = 0; mt < 2; mt++) {
#pragma unroll
        for (int t = 0; t < NTW; t++) {
            int colp = (tb + t) * 8 + 2 * tig;
            float2 bb = *(const float2*)&bias[colp];
            int r = rowBase + mt * 16 + gid;
            if (r < NNODES) {
                float2 v = {acc[mt][t][0] + bb.x, acc[mt][t][1] + bb.y};
                *(float2*)&out[(size_t)r * NOUT + colp] = v;
            }
            if (r + 8 < NNODES) {
                float2 v = {acc[mt][t][2] + bb.x, acc[mt][t][3] + bb.y};
                *(float2*)&out[(size_t)(r + 8) * NOUT + colp] = v;
            }
        }
    }
}

// Per-column sum and sum of squares over N rows.
__global__ void stats_kernel(const float* __restrict__ h) {
    int c = threadIdx.x;  // 0..127
    float s = 0.f, q = 0.f;
    for (int r = blockIdx.x; r < NNODES; r += gridDim.x) {
        float v = h[(size_t)r * FDIM + c];
        s += v;
        q += v * v;
    }
    atomicAdd(&g_stats[c], s);
    atomicAdd(&g_stats[FDIM + c], q);
}

__global__ void bnparams_kernel(const float* __restrict__ gamma,
                                const float* __restrict__ beta) {
    int c = threadIdx.x;  // 128 threads
    const float invN = 1.0f / (float)NNODES;
    float mu  = g_stats[c] * invN;
    float var = g_stats[FDIM + c] * invN - mu * mu;
    float a   = gamma[c] * rsqrtf(var + BN_EPS);
    g_scale[c] = a;
    g_shift[c] = beta[c] - mu * a;
}

__global__ void bnrelu_kernel(float4* __restrict__ h, int n4) {
    int i = blockIdx.x * blockDim.x + threadIdx.x;
    if (i >= n4) return;
    int c4 = i & (FDIM / 4 - 1);
    float4 a = ((const float4*)g_scale)[c4];
    float4 s = ((const float4*)g_shift)[c4];
    float4 v = h[i];
    v.x = fmaxf(a.x * v.x + s.x, 0.f);
    v.y = fmaxf(a.y * v.y + s.y, 0.f);
    v.z = fmaxf(a.z * v.z + s.z, 0.f);
    v.w = fmaxf(a.w * v.w + s.w, 0.f);
    h[i] = v;
}

// ---------------- launch ----------------
extern "C" void kernel_launch(void* const* d_in, const int* in_sizes, int n_in,
                              void* d_out, int out_size) {
    const float* x      = (const float*)d_in[0];
    const int*   ei     = (const int*)d_in[1];
    const float* ew     = (const float*)d_in[2];
    const float* Wl0    = (const float*)d_in[3];
    const float* Wr0    = (const float*)d_in[4];
    const float* b0     = (const float*)d_in[5];
    const float* Wl1    = (const float*)d_in[6];
    const float* Wr1    = (const float*)d_in[7];
    const float* b1     = (const float*)d_in[8];
    const float* Wl2    = (const float*)d_in[9];
    const float* Wr2    = (const float*)d_in[10];
    const float* b2     = (const float*)d_in[11];
    const float* gamma0 = (const float*)d_in[12];
    const float* beta0  = (const float*)d_in[13];
    const float* gamma1 = (const float*)d_in[14];
    const float* beta1  = (const float*)d_in[15];
    float* out = (float*)d_out;

    const int E = in_sizes[2];
    const int* src = ei;
    const int* dst = ei + E;

    float *agg, *h1, *h2, *cnt, *stats, *wph, *wpl;
    cudaGetSymbolAddress((void**)&agg,   g_agg);
    cudaGetSymbolAddress((void**)&h1,    g_h1);
    cudaGetSymbolAddress((void**)&h2,    g_h2);
    cudaGetSymbolAddress((void**)&cnt,   g_cnt);
    cudaGetSymbolAddress((void**)&stats, g_stats);
    cudaGetSymbolAddress((void**)&wph,   g_wph);
    cudaGetSymbolAddress((void**)&wpl,   g_wpl);

    auto zero = [&](float* p, int n) {
        int n4 = n / 4;
        zero_kernel<<<(n4 + 255) / 256, 256>>>((float4*)p, n4);
    };

    const int scatterBlocks = (E * 32 + 255) / 256;
    const int bnN4          = NNODES * (FDIM / 4);
    const int gemmBlocks    = (NNODES + 127) / 128;
    const int SMEM128 = 4 * 16 * 64 * 2 * (int)sizeof(float);  // 32 KB
    const int SMEM64  = 4 * 8  * 64 * 2 * (int)sizeof(float);  // 16 KB

    // pack tf32 hi/lo weights (fragment order), once per launch
    pack_w_kernel<<<(256 * 128 + 255) / 256, 256>>>(Wl0, Wr0, 128, wph,         wpl);
    pack_w_kernel<<<(256 * 128 + 255) / 256, 256>>>(Wl1, Wr1, 128, wph + 32768, wpl + 32768);
    pack_w_kernel<<<(256 * 64  + 255) / 256, 256>>>(Wl2, Wr2, 64,  wph + 65536, wpl + 65536);

    // in-degree (shared by all 3 layers)
    zero(cnt, NNODES);
    count_kernel<<<(E + 255) / 256, 256>>>(dst, E);

    // ---- layer 0 ----
    zero(agg, NNODES * FDIM);
    scatter_kernel<<<scatterBlocks, 256>>>((const float4*)x, src, dst, ew, E);
    gemm_tc<128><<<gemmBlocks, 256, SMEM128>>>(x, wph, wpl, b0, h1);
    zero(stats, 2 * FDIM);
    stats_kernel<<<1024, 128>>>(h1);
    bnparams_kernel<<<1, 128>>>(gamma0, beta0);
    bnrelu_kernel<<<(bnN4 + 255) / 256, 256>>>((float4*)h1, bnN4);

    // ---- layer 1 ----
    zero(agg, NNODES * FDIM);
    scatter_kernel<<<scatterBlocks, 256>>>((const float4*)h1, src, dst, ew, E);
    gemm_tc<128><<<gemmBlocks, 256, SMEM128>>>(h1, wph + 32768, wpl + 32768, b1, h2);
    zero(stats, 2 * FDIM);
    stats_kernel<<<1024, 128>>>(h2);
    bnparams_kernel<<<1, 128>>>(gamma1, beta1);
    bnrelu_kernel<<<(bnN4 + 255) / 256, 256>>>((float4*)h2, bnN4);

    // ---- layer 2 ----
    zero(agg, NNODES * FDIM);
    scatter_kernel<<<scatterBlocks, 256>>>((const float4*)h2, src, dst, ew, E);
    gemm_tc<64><<<gemmBlocks, 256, SMEM64>>>(h2, wph + 65536, wpl + 65536, b2, out);
}